// round 1
// baseline (speedup 1.0000x reference)
#include <cuda_runtime.h>
#include <cstdint>

// Problem constants
#define NB 64           // N = B*P
#define LL 512
#define HH 768
#define SS 16
#define M_TOTAL (NB * LL)   // 32768

// Output layout (flat float32):
//   [0, NB*HH)                      pooled_output_passages   (64*768   = 49152)
//   [49152, 49152 + NB*SS*HH)       sentence_embeddings      (1024*768 = 786432)
//   [835584, 835584 + NB*SS)        sentence_mask            (1024)
#define PASS_OFF 0
#define SENT_OFF (NB * HH)
#define MASK_OFF (NB * HH + NB * SS * HH)

// 96 MB scratch for tanh(X @ W^T + b)
__device__ float g_pooled[(size_t)M_TOTAL * HH];

// ---------------------------------------------------------------------------
// Kernel 1: fused SGEMM + bias + tanh
//   C[m, o] = tanh( sum_h X[m, h] * W[o, h] + b[o] )
// 128x128 block tile, BK=8, 256 threads, 8x8 per-thread tile.
// ---------------------------------------------------------------------------
#define BM 128
#define BN 128
#define BK 8
#define TM 8
#define TN 8

__global__ __launch_bounds__(256) void gemm_tanh_kernel(
    const float* __restrict__ A,     // X: [M_TOTAL, HH]
    const float* __restrict__ W,     // W: [HH, HH] (o rows, h cols)
    const float* __restrict__ bias)  // [HH]
{
    __shared__ float As[BK][BM];
    __shared__ float Bs[BK][BN];

    const int tid = threadIdx.x;
    const int m0 = blockIdx.y * BM;
    const int n0 = blockIdx.x * BN;

    // Load mapping: each thread loads one float4 of A-tile and one of B-tile.
    const int lrow = tid >> 1;            // 0..127
    const int lcol = (tid & 1) * 4;       // 0 or 4

    const float* Aptr = A + (size_t)(m0 + lrow) * HH + lcol;
    const float* Wptr = W + (size_t)(n0 + lrow) * HH + lcol;

    // Compute mapping: 16x16 thread grid, each owns an 8x8 output tile.
    const int tx = tid & 15;   // column group
    const int ty = tid >> 4;   // row group

    float acc[TM][TN];
#pragma unroll
    for (int i = 0; i < TM; i++)
#pragma unroll
        for (int j = 0; j < TN; j++) acc[i][j] = 0.0f;

    for (int k0 = 0; k0 < HH; k0 += BK) {
        const float4 av = *reinterpret_cast<const float4*>(Aptr + k0);
        const float4 wv = *reinterpret_cast<const float4*>(Wptr + k0);

        As[lcol + 0][lrow] = av.x;
        As[lcol + 1][lrow] = av.y;
        As[lcol + 2][lrow] = av.z;
        As[lcol + 3][lrow] = av.w;
        Bs[lcol + 0][lrow] = wv.x;
        Bs[lcol + 1][lrow] = wv.y;
        Bs[lcol + 2][lrow] = wv.z;
        Bs[lcol + 3][lrow] = wv.w;
        __syncthreads();

#pragma unroll
        for (int k = 0; k < BK; k++) {
            float ar[TM], br[TN];
            *reinterpret_cast<float4*>(&ar[0]) =
                *reinterpret_cast<const float4*>(&As[k][ty * TM]);
            *reinterpret_cast<float4*>(&ar[4]) =
                *reinterpret_cast<const float4*>(&As[k][ty * TM + 4]);
            *reinterpret_cast<float4*>(&br[0]) =
                *reinterpret_cast<const float4*>(&Bs[k][tx * TN]);
            *reinterpret_cast<float4*>(&br[4]) =
                *reinterpret_cast<const float4*>(&Bs[k][tx * TN + 4]);
#pragma unroll
            for (int i = 0; i < TM; i++)
#pragma unroll
                for (int j = 0; j < TN; j++)
                    acc[i][j] += ar[i] * br[j];
        }
        __syncthreads();
    }

    // Epilogue: bias + tanh, vectorized store to scratch.
    const int ncol = n0 + tx * TN;
    float bvals[TN];
#pragma unroll
    for (int j = 0; j < TN; j++) bvals[j] = bias[ncol + j];

#pragma unroll
    for (int i = 0; i < TM; i++) {
        const int m = m0 + ty * TM + i;
        float4 o0, o1;
        o0.x = tanhf(acc[i][0] + bvals[0]);
        o0.y = tanhf(acc[i][1] + bvals[1]);
        o0.z = tanhf(acc[i][2] + bvals[2]);
        o0.w = tanhf(acc[i][3] + bvals[3]);
        o1.x = tanhf(acc[i][4] + bvals[4]);
        o1.y = tanhf(acc[i][5] + bvals[5]);
        o1.z = tanhf(acc[i][6] + bvals[6]);
        o1.w = tanhf(acc[i][7] + bvals[7]);
        float* dst = &g_pooled[(size_t)m * HH + ncol];
        *reinterpret_cast<float4*>(dst) = o0;
        *reinterpret_cast<float4*>(dst + 4) = o1;
    }
}

// ---------------------------------------------------------------------------
// Kernel 2: span-mean pooling + passage row-0 copy + mask zeroing.
// Grid: NB * (SS + 1) blocks, 256 threads.
//   s in [0, SS)  -> sentence_embeddings[n, s] = mean over l in [start, end)
//   s == SS       -> passage copy (row l=0) + zero the mask row for n
// ---------------------------------------------------------------------------
__global__ __launch_bounds__(256) void pool_kernel(
    const int* __restrict__ spans,   // [NB, SS, 2]
    float* __restrict__ out)
{
    const int n = blockIdx.x / (SS + 1);
    const int s = blockIdx.x % (SS + 1);
    const int h = threadIdx.x;       // 256 threads, 3 columns each (768/256)

    if (s == SS) {
        const float* row0 = &g_pooled[(size_t)(n * LL) * HH];
        out[PASS_OFF + n * HH + h]       = row0[h];
        out[PASS_OFF + n * HH + h + 256] = row0[h + 256];
        out[PASS_OFF + n * HH + h + 512] = row0[h + 512];
        if (h < SS) out[MASK_OFF + n * SS + h] = 0.0f;
        return;
    }

    const int start = spans[(n * SS + s) * 2 + 0];
    const int end   = spans[(n * SS + s) * 2 + 1];
    const float inv = 1.0f / (float)(end - start);

    float a0 = 0.0f, a1 = 0.0f, a2 = 0.0f;
    const float* base = &g_pooled[(size_t)(n * LL) * HH];
    for (int l = start; l < end; l++) {
        const float* row = base + (size_t)l * HH;
        a0 += row[h];
        a1 += row[h + 256];
        a2 += row[h + 512];
    }
    float* dst = &out[SENT_OFF + (size_t)(n * SS + s) * HH];
    dst[h]       = a0 * inv;
    dst[h + 256] = a1 * inv;
    dst[h + 512] = a2 * inv;
}

// ---------------------------------------------------------------------------
// Launch
// Inputs (metadata order): hidden_states f32 [64,512,768], dense_w f32 [768,768],
//   dense_b f32 [768], attention_mask i32 [64,512] (unused), spans i32 [64,16,2]
// Output: 836608 floats, layout per offsets above.
// ---------------------------------------------------------------------------
extern "C" void kernel_launch(void* const* d_in, const int* in_sizes, int n_in,
                              void* d_out, int out_size) {
    const float* hs    = (const float*)d_in[0];
    const float* w     = (const float*)d_in[1];
    const float* b     = (const float*)d_in[2];
    const int*   spans = (const int*)d_in[4];
    float* out = (float*)d_out;

    dim3 grid(HH / BN, M_TOTAL / BM);   // (6, 256)
    gemm_tanh_kernel<<<grid, 256>>>(hs, w, b);
    pool_kernel<<<NB * (SS + 1), 256>>>(spans, out);
}

// round 3
// speedup vs baseline: 2.1997x; 2.1997x over previous
#include <cuda_runtime.h>
#include <cuda_fp16.h>
#include <cstdint>

// ---------------------------------------------------------------------------
// Problem constants
// ---------------------------------------------------------------------------
#define NB 64
#define LL 512
#define HH 768
#define SS 16
#define M_TOTAL (NB * LL)          // 32768

#define PASS_OFF 0
#define SENT_OFF (NB * HH)
#define MASK_OFF (NB * HH + NB * SS * HH)

// GEMM tiling
#define BM 128
#define BN 128
#define BK 32
#define NKCH (HH / BK)             // 24 k-chunks
#define ROWB 80                    // padded smem row stride in bytes (32 halves -> 80B)
#define TILE_B (128 * ROWB)        // 10240 bytes per operand tile
#define OFF_AH 0
#define OFF_AL (1 * TILE_B)
#define OFF_BH (2 * TILE_B)
#define OFF_BL (3 * TILE_B)
#define STAGE_B (4 * TILE_B)       // 40960
#define NSTAGE 3
#define DYN_SMEM (NSTAGE * STAGE_B)   // 122880

// ---------------------------------------------------------------------------
// Device scratch (no allocs allowed)
// ---------------------------------------------------------------------------
__device__ float  g_pooled[(size_t)M_TOTAL * HH];  // 96 MB
__device__ __half g_xh[(size_t)M_TOTAL * HH];      // 48 MB
__device__ __half g_xl[(size_t)M_TOTAL * HH];      // 48 MB
__device__ __half g_wh[HH * HH];
__device__ __half g_wl[HH * HH];

// ---------------------------------------------------------------------------
// PTX helpers
// ---------------------------------------------------------------------------
__device__ __forceinline__ uint32_t smem_u32(const void* p) {
    uint32_t a;
    asm("{ .reg .u64 t; cvta.to.shared.u64 t, %1; cvt.u32.u64 %0, t; }"
        : "=r"(a) : "l"(p));
    return a;
}

__device__ __forceinline__ void cp16(uint32_t saddr, const void* g) {
    asm volatile("cp.async.cg.shared.global [%0], [%1], 16;"
                 :: "r"(saddr), "l"(g) : "memory");
}

#define CP_COMMIT() asm volatile("cp.async.commit_group;" ::: "memory")

#define LDSM_X4(r0, r1, r2, r3, addr) \
    asm volatile("ldmatrix.sync.aligned.m8n8.x4.shared.b16 {%0,%1,%2,%3}, [%4];" \
                 : "=r"(r0), "=r"(r1), "=r"(r2), "=r"(r3) : "r"(addr))

#define MMA16816(c, a, b0, b1) \
    asm volatile("mma.sync.aligned.m16n8k16.row.col.f32.f16.f16.f32 " \
                 "{%0,%1,%2,%3}, {%4,%5,%6,%7}, {%8,%9}, {%0,%1,%2,%3};" \
                 : "+f"((c)[0]), "+f"((c)[1]), "+f"((c)[2]), "+f"((c)[3]) \
                 : "r"((a)[0]), "r"((a)[1]), "r"((a)[2]), "r"((a)[3]), \
                   "r"(b0), "r"(b1))

// ---------------------------------------------------------------------------
// fp32 -> (fp16 hi, fp16 lo) split conversion
// ---------------------------------------------------------------------------
__global__ __launch_bounds__(256) void convert_x_kernel(const float* __restrict__ src) {
    size_t i = (size_t)blockIdx.x * blockDim.x + threadIdx.x;
    const size_t n4 = (size_t)M_TOTAL * HH / 4;
    if (i >= n4) return;
    float4 v = reinterpret_cast<const float4*>(src)[i];
    __half h0 = __float2half_rn(v.x), h1 = __float2half_rn(v.y);
    __half h2 = __float2half_rn(v.z), h3 = __float2half_rn(v.w);
    __half l0 = __float2half_rn(v.x - __half2float(h0));
    __half l1 = __float2half_rn(v.y - __half2float(h1));
    __half l2 = __float2half_rn(v.z - __half2float(h2));
    __half l3 = __float2half_rn(v.w - __half2float(h3));
    reinterpret_cast<__half2*>(g_xh)[2 * i]     = __half2(h0, h1);
    reinterpret_cast<__half2*>(g_xh)[2 * i + 1] = __half2(h2, h3);
    reinterpret_cast<__half2*>(g_xl)[2 * i]     = __half2(l0, l1);
    reinterpret_cast<__half2*>(g_xl)[2 * i + 1] = __half2(l2, l3);
}

__global__ __launch_bounds__(256) void convert_w_kernel(const float* __restrict__ src) {
    size_t i = (size_t)blockIdx.x * blockDim.x + threadIdx.x;
    const size_t n4 = (size_t)HH * HH / 4;
    if (i >= n4) return;
    float4 v = reinterpret_cast<const float4*>(src)[i];
    __half h0 = __float2half_rn(v.x), h1 = __float2half_rn(v.y);
    __half h2 = __float2half_rn(v.z), h3 = __float2half_rn(v.w);
    __half l0 = __float2half_rn(v.x - __half2float(h0));
    __half l1 = __float2half_rn(v.y - __half2float(h1));
    __half l2 = __float2half_rn(v.z - __half2float(h2));
    __half l3 = __float2half_rn(v.w - __half2float(h3));
    reinterpret_cast<__half2*>(g_wh)[2 * i]     = __half2(h0, h1);
    reinterpret_cast<__half2*>(g_wh)[2 * i + 1] = __half2(h2, h3);
    reinterpret_cast<__half2*>(g_wl)[2 * i]     = __half2(l0, l1);
    reinterpret_cast<__half2*>(g_wl)[2 * i + 1] = __half2(l2, l3);
}

// ---------------------------------------------------------------------------
// GEMM: g_pooled[m, n] = tanh( X[m, :] . W[n, :] + b[n] )
// fp16x3: Ah*Bh + Ah*Bl + Al*Bh, fp32 accumulate via mma.sync.m16n8k16.
// 128x128 CTA tile, BK=32, 3-stage cp.async, 8 warps of 32x64.
// ---------------------------------------------------------------------------
__device__ __forceinline__ void load_stage(uint32_t sb, int k0, int m0, int n0) {
    const int t = threadIdx.x;
#pragma unroll
    for (int i = 0; i < 2; i++) {
        int c = t + 256 * i;              // 512 (row, chunk) pairs
        int row = c >> 2, ch = c & 3;
        uint32_t so = (uint32_t)(row * ROWB + ch * 16);
        size_t ga = (size_t)(m0 + row) * HH + k0 + ch * 8;
        size_t gb = (size_t)(n0 + row) * HH + k0 + ch * 8;
        cp16(sb + OFF_AH + so, g_xh + ga);
        cp16(sb + OFF_AL + so, g_xl + ga);
        cp16(sb + OFF_BH + so, g_wh + gb);
        cp16(sb + OFF_BL + so, g_wl + gb);
    }
    CP_COMMIT();
}

__global__ __launch_bounds__(256, 1) void gemm_kernel(const float* __restrict__ bias) {
    extern __shared__ char dsm[];
    __shared__ float s_bias[BN];

    const int tid = threadIdx.x;
    const int wid = tid >> 5;
    const int lane = tid & 31;
    const int m0 = blockIdx.y * BM;
    const int n0 = blockIdx.x * BN;

    const int mw = (wid & 3) * 32;   // warp m offset (4 warps over M)
    const int nw = (wid >> 2) * 64;  // warp n offset (2 warps over N)

    const uint32_t sbase = smem_u32(dsm);

    if (tid < BN) s_bias[tid] = bias[n0 + tid];

    float c[2][8][4];
#pragma unroll
    for (int mt = 0; mt < 2; mt++)
#pragma unroll
        for (int j = 0; j < 8; j++)
#pragma unroll
            for (int r = 0; r < 4; r++) c[mt][j][r] = 0.0f;

    // Per-lane ldmatrix address components
    const uint32_t a_row = (uint32_t)(mw + (lane & 15)) * ROWB;
    const uint32_t a_col = ((lane >> 4) & 1) * 16;
    const uint32_t b_row = (uint32_t)(nw + (lane & 7) + ((lane >> 4) & 1) * 8) * ROWB;
    const uint32_t b_col = ((lane >> 3) & 1) * 16;

    // Prologue: stages 0 and 1
    load_stage(sbase + 0 * STAGE_B, 0 * BK, m0, n0);
    load_stage(sbase + 1 * STAGE_B, 1 * BK, m0, n0);

    for (int kt = 0; kt < NKCH; kt++) {
        if (kt == NKCH - 1) asm volatile("cp.async.wait_group 0;" ::: "memory");
        else                asm volatile("cp.async.wait_group 1;" ::: "memory");
        __syncthreads();

        const uint32_t sb = sbase + (uint32_t)(kt % NSTAGE) * STAGE_B;

        if (kt + 2 < NKCH)
            load_stage(sbase + (uint32_t)((kt + 2) % NSTAGE) * STAGE_B,
                       (kt + 2) * BK, m0, n0);

#pragma unroll
        for (int ks = 0; ks < 2; ks++) {
            const uint32_t kb = (uint32_t)ks * 32;
            uint32_t ah[2][4], al[2][4], bh[4][4], bl[4][4];
#pragma unroll
            for (int mt = 0; mt < 2; mt++) {
                uint32_t ra = sb + a_row + (uint32_t)(mt * 16) * ROWB + kb + a_col;
                LDSM_X4(ah[mt][0], ah[mt][1], ah[mt][2], ah[mt][3], ra + OFF_AH);
                LDSM_X4(al[mt][0], al[mt][1], al[mt][2], al[mt][3], ra + OFF_AL);
            }
#pragma unroll
            for (int nt = 0; nt < 4; nt++) {
                uint32_t rb = sb + b_row + (uint32_t)(nt * 16) * ROWB + kb + b_col;
                LDSM_X4(bh[nt][0], bh[nt][1], bh[nt][2], bh[nt][3], rb + OFF_BH);
                LDSM_X4(bl[nt][0], bl[nt][1], bl[nt][2], bl[nt][3], rb + OFF_BL);
            }
#pragma unroll
            for (int mt = 0; mt < 2; mt++) {
#pragma unroll
                for (int nt = 0; nt < 4; nt++) {
                    // n8 tile 2*nt   -> regs {0,1}; tile 2*nt+1 -> regs {2,3}
                    MMA16816(c[mt][2 * nt],     ah[mt], bh[nt][0], bh[nt][1]);
                    MMA16816(c[mt][2 * nt + 1], ah[mt], bh[nt][2], bh[nt][3]);
                    MMA16816(c[mt][2 * nt],     ah[mt], bl[nt][0], bl[nt][1]);
                    MMA16816(c[mt][2 * nt + 1], ah[mt], bl[nt][2], bl[nt][3]);
                    MMA16816(c[mt][2 * nt],     al[mt], bh[nt][0], bh[nt][1]);
                    MMA16816(c[mt][2 * nt + 1], al[mt], bh[nt][2], bh[nt][3]);
                }
            }
        }
    }
    __syncthreads();

    // Epilogue: bias + tanh, write fp32 to scratch.
    const int g = lane >> 2;
    const int tg = lane & 3;
#pragma unroll
    for (int mt = 0; mt < 2; mt++) {
        const int mrow = m0 + mw + mt * 16 + g;
#pragma unroll
        for (int j = 0; j < 8; j++) {
            const int ncol = nw + j * 8 + tg * 2;      // within [0, 128)
            const float b0 = s_bias[ncol];
            const float b1 = s_bias[ncol + 1];
            float2 lo, hi;
            lo.x = tanhf(c[mt][j][0] + b0);
            lo.y = tanhf(c[mt][j][1] + b1);
            hi.x = tanhf(c[mt][j][2] + b0);
            hi.y = tanhf(c[mt][j][3] + b1);
            *reinterpret_cast<float2*>(&g_pooled[(size_t)mrow * HH + n0 + ncol]) = lo;
            *reinterpret_cast<float2*>(&g_pooled[(size_t)(mrow + 8) * HH + n0 + ncol]) = hi;
        }
    }
}

// ---------------------------------------------------------------------------
// Span-mean pooling + passage copy + mask.
// ---------------------------------------------------------------------------
#define PB_SENT (NB * SS * 2)   // 2048

__global__ __launch_bounds__(128) void pool_kernel(
    const int* __restrict__ spans, float* __restrict__ out) {
    const int bx = blockIdx.x;
    const int tid = threadIdx.x;

    if (bx < PB_SENT) {
        const int n = bx >> 5;
        const int rem = bx & 31;
        const int s = rem >> 1;
        const int half = rem & 1;
        const int h = half * 384 + tid;

        const int start = spans[(n * SS + s) * 2 + 0];
        const int end   = spans[(n * SS + s) * 2 + 1];
        const float inv = 1.0f / (float)(end - start);

        const float* base = &g_pooled[(size_t)(n * LL) * HH];
        float a0 = 0.0f, a1 = 0.0f, a2 = 0.0f;
        int l = start;
        for (; l + 1 < end; l += 2) {
            const float* r0 = base + (size_t)l * HH;
            const float* r1 = r0 + HH;
            a0 += r0[h]       + r1[h];
            a1 += r0[h + 128] + r1[h + 128];
            a2 += r0[h + 256] + r1[h + 256];
        }
        if (l < end) {
            const float* r0 = base + (size_t)l * HH;
            a0 += r0[h];
            a1 += r0[h + 128];
            a2 += r0[h + 256];
        }
        float* dst = &out[SENT_OFF + (size_t)(n * SS + s) * HH + half * 384];
        dst[tid]       = a0 * inv;
        dst[tid + 128] = a1 * inv;
        dst[tid + 256] = a2 * inv;
    } else {
        const int n = bx - PB_SENT;
        const float* row0 = &g_pooled[(size_t)(n * LL) * HH];
#pragma unroll
        for (int j = 0; j < 6; j++)
            out[PASS_OFF + n * HH + tid + 128 * j] = row0[tid + 128 * j];
        if (tid < SS) out[MASK_OFF + n * SS + tid] = 0.0f;
    }
}

// ---------------------------------------------------------------------------
// Launch
// ---------------------------------------------------------------------------
extern "C" void kernel_launch(void* const* d_in, const int* in_sizes, int n_in,
                              void* d_out, int out_size) {
    const float* hs    = (const float*)d_in[0];
    const float* w     = (const float*)d_in[1];
    const float* b     = (const float*)d_in[2];
    const int*   spans = (const int*)d_in[4];
    float* out = (float*)d_out;

    cudaFuncSetAttribute(gemm_kernel,
                         cudaFuncAttributeMaxDynamicSharedMemorySize, DYN_SMEM);

    const int x4 = M_TOTAL * HH / 4;
    const int w4 = HH * HH / 4;
    convert_x_kernel<<<(x4 + 255) / 256, 256>>>(hs);
    convert_w_kernel<<<(w4 + 255) / 256, 256>>>(w);

    dim3 grid(HH / BN, M_TOTAL / BM);     // (6, 256)
    gemm_kernel<<<grid, 256, DYN_SMEM>>>(b);

    pool_kernel<<<PB_SENT + NB, 128>>>(spans, out);
}

// round 4
// speedup vs baseline: 2.3340x; 1.0611x over previous
#include <cuda_runtime.h>
#include <cuda_fp16.h>
#include <cstdint>

// ---------------------------------------------------------------------------
// Problem constants
// ---------------------------------------------------------------------------
#define NB 64
#define LL 512
#define HH 768
#define SS 16
#define M_TOTAL (NB * LL)          // 32768

#define PASS_OFF 0
#define SENT_OFF (NB * HH)
#define MASK_OFF (NB * HH + NB * SS * HH)

// GEMM tiling: CTA 128x256, warp 64x64 (8 warps, 2x4), BK=32, 3 stages
#define BM 128
#define BN 256
#define BK 32
#define NKCH (HH / BK)             // 24
#define ROWB 80                    // 32 halves (64B) padded to 80B
#define OFF_AH 0
#define OFF_AL (128 * ROWB)                    // 10240
#define OFF_BH (2 * 128 * ROWB)                // 20480
#define OFF_BL (2 * 128 * ROWB + 256 * ROWB)   // 40960
#define STAGE_B (2 * 128 * ROWB + 2 * 256 * ROWB)  // 61440
#define NSTAGE 3
#define DYN_SMEM (NSTAGE * STAGE_B)            // 184320

// ---------------------------------------------------------------------------
// Device scratch
// ---------------------------------------------------------------------------
__device__ float  g_pooled[(size_t)M_TOTAL * HH];  // 96 MB
__device__ __half g_xh[(size_t)M_TOTAL * HH];      // 48 MB
__device__ __half g_xl[(size_t)M_TOTAL * HH];      // 48 MB
__device__ __half g_wh[HH * HH];
__device__ __half g_wl[HH * HH];

// ---------------------------------------------------------------------------
// PTX helpers
// ---------------------------------------------------------------------------
__device__ __forceinline__ uint32_t smem_u32(const void* p) {
    uint32_t a;
    asm("{ .reg .u64 t; cvta.to.shared.u64 t, %1; cvt.u32.u64 %0, t; }"
        : "=r"(a) : "l"(p));
    return a;
}

__device__ __forceinline__ void cp16(uint32_t saddr, const void* g) {
    asm volatile("cp.async.cg.shared.global [%0], [%1], 16;"
                 :: "r"(saddr), "l"(g) : "memory");
}

#define CP_COMMIT() asm volatile("cp.async.commit_group;" ::: "memory")

#define LDSM_X4(r0, r1, r2, r3, addr) \
    asm volatile("ldmatrix.sync.aligned.m8n8.x4.shared.b16 {%0,%1,%2,%3}, [%4];" \
                 : "=r"(r0), "=r"(r1), "=r"(r2), "=r"(r3) : "r"(addr))

#define MMA16816(c, a, b0, b1) \
    asm volatile("mma.sync.aligned.m16n8k16.row.col.f32.f16.f16.f32 " \
                 "{%0,%1,%2,%3}, {%4,%5,%6,%7}, {%8,%9}, {%0,%1,%2,%3};" \
                 : "+f"((c)[0]), "+f"((c)[1]), "+f"((c)[2]), "+f"((c)[3]) \
                 : "r"((a)[0]), "r"((a)[1]), "r"((a)[2]), "r"((a)[3]), \
                   "r"(b0), "r"(b1))

// ---------------------------------------------------------------------------
// fp32 -> (fp16 hi, fp16 lo) split conversion
// ---------------------------------------------------------------------------
__global__ __launch_bounds__(256) void convert_x_kernel(const float* __restrict__ src) {
    size_t i = (size_t)blockIdx.x * blockDim.x + threadIdx.x;
    const size_t n4 = (size_t)M_TOTAL * HH / 4;
    if (i >= n4) return;
    float4 v = reinterpret_cast<const float4*>(src)[i];
    __half h0 = __float2half_rn(v.x), h1 = __float2half_rn(v.y);
    __half h2 = __float2half_rn(v.z), h3 = __float2half_rn(v.w);
    __half l0 = __float2half_rn(v.x - __half2float(h0));
    __half l1 = __float2half_rn(v.y - __half2float(h1));
    __half l2 = __float2half_rn(v.z - __half2float(h2));
    __half l3 = __float2half_rn(v.w - __half2float(h3));
    reinterpret_cast<__half2*>(g_xh)[2 * i]     = __half2(h0, h1);
    reinterpret_cast<__half2*>(g_xh)[2 * i + 1] = __half2(h2, h3);
    reinterpret_cast<__half2*>(g_xl)[2 * i]     = __half2(l0, l1);
    reinterpret_cast<__half2*>(g_xl)[2 * i + 1] = __half2(l2, l3);
}

__global__ __launch_bounds__(256) void convert_w_kernel(const float* __restrict__ src) {
    size_t i = (size_t)blockIdx.x * blockDim.x + threadIdx.x;
    const size_t n4 = (size_t)HH * HH / 4;
    if (i >= n4) return;
    float4 v = reinterpret_cast<const float4*>(src)[i];
    __half h0 = __float2half_rn(v.x), h1 = __float2half_rn(v.y);
    __half h2 = __float2half_rn(v.z), h3 = __float2half_rn(v.w);
    __half l0 = __float2half_rn(v.x - __half2float(h0));
    __half l1 = __float2half_rn(v.y - __half2float(h1));
    __half l2 = __float2half_rn(v.z - __half2float(h2));
    __half l3 = __float2half_rn(v.w - __half2float(h3));
    reinterpret_cast<__half2*>(g_wh)[2 * i]     = __half2(h0, h1);
    reinterpret_cast<__half2*>(g_wh)[2 * i + 1] = __half2(h2, h3);
    reinterpret_cast<__half2*>(g_wl)[2 * i]     = __half2(l0, l1);
    reinterpret_cast<__half2*>(g_wl)[2 * i + 1] = __half2(l2, l3);
}

// ---------------------------------------------------------------------------
// GEMM: g_pooled[m, n] = tanh( X[m, :] . W[n, :] + b[n] )
// fp16x3 via mma.sync.m16n8k16, CTA 128x256, warp 64x64.
// ---------------------------------------------------------------------------
__device__ __forceinline__ void load_stage(uint32_t sb, int k0, int m0, int n0) {
    const int t = threadIdx.x;
    // A: 128 rows x 4 chunks (hi & lo) = 512 pairs -> 2 iters of 256
#pragma unroll
    for (int i = 0; i < 2; i++) {
        int c = t + 256 * i;
        int row = c >> 2, ch = c & 3;
        uint32_t so = (uint32_t)(row * ROWB + ch * 16);
        size_t ga = (size_t)(m0 + row) * HH + k0 + ch * 8;
        cp16(sb + OFF_AH + so, g_xh + ga);
        cp16(sb + OFF_AL + so, g_xl + ga);
    }
    // B: 256 rows x 4 chunks (hi & lo) = 1024 pairs -> 4 iters
#pragma unroll
    for (int i = 0; i < 4; i++) {
        int c = t + 256 * i;
        int row = c >> 2, ch = c & 3;
        uint32_t so = (uint32_t)(row * ROWB + ch * 16);
        size_t gb = (size_t)(n0 + row) * HH + k0 + ch * 8;
        cp16(sb + OFF_BH + so, g_wh + gb);
        cp16(sb + OFF_BL + so, g_wl + gb);
    }
    CP_COMMIT();
}

__global__ __launch_bounds__(256, 1) void gemm_kernel(const float* __restrict__ bias) {
    extern __shared__ char dsm[];
    __shared__ float s_bias[BN];

    const int tid = threadIdx.x;
    const int wid = tid >> 5;
    const int lane = tid & 31;
    const int m0 = blockIdx.y * BM;
    const int n0 = blockIdx.x * BN;

    const int mw = (wid & 1) * 64;   // 2 warps over M
    const int nw = (wid >> 1) * 64;  // 4 warps over N

    const uint32_t sbase = smem_u32(dsm);

    s_bias[tid] = bias[n0 + tid];

    float c[4][8][4];
#pragma unroll
    for (int mt = 0; mt < 4; mt++)
#pragma unroll
        for (int j = 0; j < 8; j++)
#pragma unroll
            for (int r = 0; r < 4; r++) c[mt][j][r] = 0.0f;

    // Per-lane ldmatrix address components
    const uint32_t a_row = (uint32_t)(mw + (lane & 15)) * ROWB;
    const uint32_t a_col = ((lane >> 4) & 1) * 16;
    const uint32_t b_row = (uint32_t)(nw + (lane & 7) + ((lane >> 4) & 1) * 8) * ROWB;
    const uint32_t b_col = ((lane >> 3) & 1) * 16;

    load_stage(sbase + 0 * STAGE_B, 0 * BK, m0, n0);
    load_stage(sbase + 1 * STAGE_B, 1 * BK, m0, n0);

    for (int kt = 0; kt < NKCH; kt++) {
        if (kt == NKCH - 1) asm volatile("cp.async.wait_group 0;" ::: "memory");
        else                asm volatile("cp.async.wait_group 1;" ::: "memory");
        __syncthreads();

        const uint32_t sb = sbase + (uint32_t)(kt % NSTAGE) * STAGE_B;

        if (kt + 2 < NKCH)
            load_stage(sbase + (uint32_t)((kt + 2) % NSTAGE) * STAGE_B,
                       (kt + 2) * BK, m0, n0);

#pragma unroll
        for (int ks = 0; ks < 2; ks++) {
            const uint32_t kb = (uint32_t)ks * 32;   // 16 halves = 32 bytes
            uint32_t ah[4][4], al[4][4], bh[4][4], bl[4][4];
#pragma unroll
            for (int mt = 0; mt < 4; mt++) {
                uint32_t ra = sb + a_row + (uint32_t)(mt * 16) * ROWB + kb + a_col;
                LDSM_X4(ah[mt][0], ah[mt][1], ah[mt][2], ah[mt][3], ra + OFF_AH);
                LDSM_X4(al[mt][0], al[mt][1], al[mt][2], al[mt][3], ra + OFF_AL);
            }
#pragma unroll
            for (int nt = 0; nt < 4; nt++) {
                uint32_t rb = sb + b_row + (uint32_t)(nt * 16) * ROWB + kb + b_col;
                LDSM_X4(bh[nt][0], bh[nt][1], bh[nt][2], bh[nt][3], rb + OFF_BH);
                LDSM_X4(bl[nt][0], bl[nt][1], bl[nt][2], bl[nt][3], rb + OFF_BL);
            }
#pragma unroll
            for (int mt = 0; mt < 4; mt++) {
#pragma unroll
                for (int nt = 0; nt < 4; nt++) {
                    MMA16816(c[mt][2 * nt],     ah[mt], bh[nt][0], bh[nt][1]);
                    MMA16816(c[mt][2 * nt + 1], ah[mt], bh[nt][2], bh[nt][3]);
                    MMA16816(c[mt][2 * nt],     ah[mt], bl[nt][0], bl[nt][1]);
                    MMA16816(c[mt][2 * nt + 1], ah[mt], bl[nt][2], bl[nt][3]);
                    MMA16816(c[mt][2 * nt],     al[mt], bh[nt][0], bh[nt][1]);
                    MMA16816(c[mt][2 * nt + 1], al[mt], bh[nt][2], bh[nt][3]);
                }
            }
        }
    }
    __syncthreads();

    // Epilogue: bias + tanh, fp32 stores to scratch.
    const int g = lane >> 2;
    const int tg = lane & 3;
#pragma unroll
    for (int mt = 0; mt < 4; mt++) {
        const int mrow = m0 + mw + mt * 16 + g;
#pragma unroll
        for (int j = 0; j < 8; j++) {
            const int ncol = nw + j * 8 + tg * 2;
            const float b0 = s_bias[ncol];
            const float b1 = s_bias[ncol + 1];
            float2 lo, hi;
            lo.x = tanhf(c[mt][j][0] + b0);
            lo.y = tanhf(c[mt][j][1] + b1);
            hi.x = tanhf(c[mt][j][2] + b0);
            hi.y = tanhf(c[mt][j][3] + b1);
            *reinterpret_cast<float2*>(&g_pooled[(size_t)mrow * HH + n0 + ncol]) = lo;
            *reinterpret_cast<float2*>(&g_pooled[(size_t)(mrow + 8) * HH + n0 + ncol]) = hi;
        }
    }
}

// ---------------------------------------------------------------------------
// Span-mean pooling + passage copy + mask. 192 threads, float4 per thread.
// ---------------------------------------------------------------------------
#define PB_SENT (NB * SS)   // 1024

__global__ __launch_bounds__(192) void pool_kernel(
    const int* __restrict__ spans, float* __restrict__ out) {
    const int bx = blockIdx.x;
    const int tid = threadIdx.x;

    if (bx < PB_SENT) {
        const int n = bx >> 4;
        const int s = bx & 15;

        const int start = spans[(n * SS + s) * 2 + 0];
        const int end   = spans[(n * SS + s) * 2 + 1];
        const float inv = 1.0f / (float)(end - start);

        const float* base = &g_pooled[(size_t)(n * LL) * HH + 4 * tid];
        float4 a = make_float4(0.f, 0.f, 0.f, 0.f);
        int l = start;
        for (; l + 1 < end; l += 2) {
            float4 v0 = *reinterpret_cast<const float4*>(base + (size_t)l * HH);
            float4 v1 = *reinterpret_cast<const float4*>(base + (size_t)(l + 1) * HH);
            a.x += v0.x + v1.x;
            a.y += v0.y + v1.y;
            a.z += v0.z + v1.z;
            a.w += v0.w + v1.w;
        }
        if (l < end) {
            float4 v0 = *reinterpret_cast<const float4*>(base + (size_t)l * HH);
            a.x += v0.x; a.y += v0.y; a.z += v0.z; a.w += v0.w;
        }
        a.x *= inv; a.y *= inv; a.z *= inv; a.w *= inv;
        *reinterpret_cast<float4*>(&out[SENT_OFF + (size_t)(n * SS + s) * HH + 4 * tid]) = a;
    } else {
        const int n = bx - PB_SENT;
        const float4 v = *reinterpret_cast<const float4*>(
            &g_pooled[(size_t)(n * LL) * HH + 4 * tid]);
        *reinterpret_cast<float4*>(&out[PASS_OFF + n * HH + 4 * tid]) = v;
        if (tid < SS) out[MASK_OFF + n * SS + tid] = 0.0f;
    }
}

// ---------------------------------------------------------------------------
// Launch
// ---------------------------------------------------------------------------
extern "C" void kernel_launch(void* const* d_in, const int* in_sizes, int n_in,
                              void* d_out, int out_size) {
    const float* hs    = (const float*)d_in[0];
    const float* w     = (const float*)d_in[1];
    const float* b     = (const float*)d_in[2];
    const int*   spans = (const int*)d_in[4];
    float* out = (float*)d_out;

    cudaFuncSetAttribute(gemm_kernel,
                         cudaFuncAttributeMaxDynamicSharedMemorySize, DYN_SMEM);

    const int x4 = M_TOTAL * HH / 4;
    const int w4 = HH * HH / 4;
    convert_x_kernel<<<(x4 + 255) / 256, 256>>>(hs);
    convert_w_kernel<<<(w4 + 255) / 256, 256>>>(w);

    dim3 grid(HH / BN, M_TOTAL / BM);     // (3, 256)
    gemm_kernel<<<grid, 256, DYN_SMEM>>>(b);

    pool_kernel<<<PB_SENT + NB, 192>>>(spans, out);
}

// round 5
// speedup vs baseline: 3.4456x; 1.4762x over previous
#include <cuda_runtime.h>
#include <cuda_fp16.h>
#include <cstdint>

// ---------------------------------------------------------------------------
// Problem constants
// ---------------------------------------------------------------------------
#define NB 64
#define LL 512
#define SS 16
#define HH 768
#define M_TOTAL (NB * LL)          // 32768

#define PASS_OFF 0
#define SENT_OFF (NB * HH)
#define MASK_OFF (NB * HH + NB * SS * HH)

// GEMM tiling: CTA 128x128, warp 32x64 (8 warps: 4 over M, 2 over N), BK=32
#define BM 128
#define BN 128
#define BK 32
#define NKCH (HH / BK)             // 24
#define ROWB 80                    // 32 halves (64B) padded to 80B
#define OFF_AH 0
#define OFF_BH (128 * ROWB)        // 10240
#define OFF_BL (2 * 128 * ROWB)    // 20480
#define STAGE_B (3 * 128 * ROWB)   // 30720
#define NSTAGE 2
#define DYN_SMEM (NSTAGE * STAGE_B)   // 61440 -> 2 CTAs/SM

// ---------------------------------------------------------------------------
// Device scratch
// ---------------------------------------------------------------------------
__device__ float  g_pooled[(size_t)M_TOTAL * HH];  // 96 MB
__device__ __half g_xh[(size_t)M_TOTAL * HH];      // 48 MB (hi only)
__device__ __half g_wh[HH * HH];
__device__ __half g_wl[HH * HH];

// ---------------------------------------------------------------------------
// PTX helpers
// ---------------------------------------------------------------------------
__device__ __forceinline__ uint32_t smem_u32(const void* p) {
    uint32_t a;
    asm("{ .reg .u64 t; cvta.to.shared.u64 t, %1; cvt.u32.u64 %0, t; }"
        : "=r"(a) : "l"(p));
    return a;
}

__device__ __forceinline__ void cp16(uint32_t saddr, const void* g) {
    asm volatile("cp.async.cg.shared.global [%0], [%1], 16;"
                 :: "r"(saddr), "l"(g) : "memory");
}

#define CP_COMMIT() asm volatile("cp.async.commit_group;" ::: "memory")

#define LDSM_X4(r0, r1, r2, r3, addr) \
    asm volatile("ldmatrix.sync.aligned.m8n8.x4.shared.b16 {%0,%1,%2,%3}, [%4];" \
                 : "=r"(r0), "=r"(r1), "=r"(r2), "=r"(r3) : "r"(addr))

#define MMA16816(c, a, b0, b1) \
    asm volatile("mma.sync.aligned.m16n8k16.row.col.f32.f16.f16.f32 " \
                 "{%0,%1,%2,%3}, {%4,%5,%6,%7}, {%8,%9}, {%0,%1,%2,%3};" \
                 : "+f"((c)[0]), "+f"((c)[1]), "+f"((c)[2]), "+f"((c)[3]) \
                 : "r"((a)[0]), "r"((a)[1]), "r"((a)[2]), "r"((a)[3]), \
                   "r"(b0), "r"(b1))

// ---------------------------------------------------------------------------
// Conversions: X -> fp16 hi only; W -> fp16 (hi, lo)
// ---------------------------------------------------------------------------
__global__ __launch_bounds__(256) void convert_x_kernel(const float* __restrict__ src) {
    size_t i = (size_t)blockIdx.x * blockDim.x + threadIdx.x;
    const size_t n4 = (size_t)M_TOTAL * HH / 4;
    if (i >= n4) return;
    float4 v = reinterpret_cast<const float4*>(src)[i];
    __half h0 = __float2half_rn(v.x), h1 = __float2half_rn(v.y);
    __half h2 = __float2half_rn(v.z), h3 = __float2half_rn(v.w);
    reinterpret_cast<__half2*>(g_xh)[2 * i]     = __half2(h0, h1);
    reinterpret_cast<__half2*>(g_xh)[2 * i + 1] = __half2(h2, h3);
}

__global__ __launch_bounds__(256) void convert_w_kernel(const float* __restrict__ src) {
    size_t i = (size_t)blockIdx.x * blockDim.x + threadIdx.x;
    const size_t n4 = (size_t)HH * HH / 4;
    if (i >= n4) return;
    float4 v = reinterpret_cast<const float4*>(src)[i];
    __half h0 = __float2half_rn(v.x), h1 = __float2half_rn(v.y);
    __half h2 = __float2half_rn(v.z), h3 = __float2half_rn(v.w);
    __half l0 = __float2half_rn(v.x - __half2float(h0));
    __half l1 = __float2half_rn(v.y - __half2float(h1));
    __half l2 = __float2half_rn(v.z - __half2float(h2));
    __half l3 = __float2half_rn(v.w - __half2float(h3));
    reinterpret_cast<__half2*>(g_wh)[2 * i]     = __half2(h0, h1);
    reinterpret_cast<__half2*>(g_wh)[2 * i + 1] = __half2(h2, h3);
    reinterpret_cast<__half2*>(g_wl)[2 * i]     = __half2(l0, l1);
    reinterpret_cast<__half2*>(g_wl)[2 * i + 1] = __half2(l2, l3);
}

// ---------------------------------------------------------------------------
// GEMM: g_pooled[m, n] = tanh( X[m, :] . W[n, :] + b[n] )
// fp16x2: Ah*Bh + Ah*Bl (W kept exact, X hi only), fp32 accumulate.
// CTA 128x128, warp 32x64, 2-stage cp.async, 2 CTAs/SM.
// ---------------------------------------------------------------------------
__device__ __forceinline__ void load_stage(uint32_t sb, int k0, int m0, int n0) {
    const int t = threadIdx.x;
    // A hi: 128 rows x 4 chunks = 512 -> 2 iters
#pragma unroll
    for (int i = 0; i < 2; i++) {
        int c = t + 256 * i;
        int row = c >> 2, ch = c & 3;
        uint32_t so = (uint32_t)(row * ROWB + ch * 16);
        cp16(sb + OFF_AH + so, g_xh + (size_t)(m0 + row) * HH + k0 + ch * 8);
    }
    // B hi + lo: 128 rows x 4 chunks each
#pragma unroll
    for (int i = 0; i < 2; i++) {
        int c = t + 256 * i;
        int row = c >> 2, ch = c & 3;
        uint32_t so = (uint32_t)(row * ROWB + ch * 16);
        size_t gb = (size_t)(n0 + row) * HH + k0 + ch * 8;
        cp16(sb + OFF_BH + so, g_wh + gb);
        cp16(sb + OFF_BL + so, g_wl + gb);
    }
    CP_COMMIT();
}

__global__ __launch_bounds__(256, 2) void gemm_kernel(const float* __restrict__ bias) {
    extern __shared__ char dsm[];
    __shared__ float s_bias[BN];

    const int tid = threadIdx.x;
    const int wid = tid >> 5;
    const int lane = tid & 31;
    const int m0 = blockIdx.y * BM;
    const int n0 = blockIdx.x * BN;

    const int mw = (wid >> 1) * 32;  // 4 warps over M
    const int nw = (wid & 1) * 64;   // 2 warps over N

    const uint32_t sbase = smem_u32(dsm);

    if (tid < BN) s_bias[tid] = bias[n0 + tid];

    float c[2][8][4];
#pragma unroll
    for (int mt = 0; mt < 2; mt++)
#pragma unroll
        for (int j = 0; j < 8; j++)
#pragma unroll
            for (int r = 0; r < 4; r++) c[mt][j][r] = 0.0f;

    const uint32_t a_row = (uint32_t)(mw + (lane & 15)) * ROWB;
    const uint32_t a_col = ((lane >> 4) & 1) * 16;
    const uint32_t b_row = (uint32_t)(nw + (lane & 7) + ((lane >> 4) & 1) * 8) * ROWB;
    const uint32_t b_col = ((lane >> 3) & 1) * 16;

    load_stage(sbase, 0, m0, n0);

    for (int kt = 0; kt < NKCH; kt++) {
        __syncthreads();   // buffer (kt+1)&1 free (compute on it finished 2 iters ago)
        if (kt + 1 < NKCH)
            load_stage(sbase + (uint32_t)((kt + 1) & 1) * STAGE_B, (kt + 1) * BK, m0, n0);
        if (kt + 1 < NKCH) asm volatile("cp.async.wait_group 1;" ::: "memory");
        else               asm volatile("cp.async.wait_group 0;" ::: "memory");
        __syncthreads();

        const uint32_t sb = sbase + (uint32_t)(kt & 1) * STAGE_B;

#pragma unroll
        for (int ks = 0; ks < 2; ks++) {
            const uint32_t kb = (uint32_t)ks * 32;   // 16 halves = 32 bytes
            uint32_t ah[2][4], bh[4][4], bl[4][4];
#pragma unroll
            for (int mt = 0; mt < 2; mt++) {
                uint32_t ra = sb + OFF_AH + a_row + (uint32_t)(mt * 16) * ROWB + kb + a_col;
                LDSM_X4(ah[mt][0], ah[mt][1], ah[mt][2], ah[mt][3], ra);
            }
#pragma unroll
            for (int nt = 0; nt < 4; nt++) {
                uint32_t rb = sb + b_row + (uint32_t)(nt * 16) * ROWB + kb + b_col;
                LDSM_X4(bh[nt][0], bh[nt][1], bh[nt][2], bh[nt][3], rb + OFF_BH);
                LDSM_X4(bl[nt][0], bl[nt][1], bl[nt][2], bl[nt][3], rb + OFF_BL);
            }
#pragma unroll
            for (int mt = 0; mt < 2; mt++) {
#pragma unroll
                for (int nt = 0; nt < 4; nt++) {
                    MMA16816(c[mt][2 * nt],     ah[mt], bh[nt][0], bh[nt][1]);
                    MMA16816(c[mt][2 * nt + 1], ah[mt], bh[nt][2], bh[nt][3]);
                    MMA16816(c[mt][2 * nt],     ah[mt], bl[nt][0], bl[nt][1]);
                    MMA16816(c[mt][2 * nt + 1], ah[mt], bl[nt][2], bl[nt][3]);
                }
            }
        }
    }
    __syncthreads();

    // Epilogue: bias + tanh, fp32 stores to scratch.
    const int g = lane >> 2;
    const int tg = lane & 3;
#pragma unroll
    for (int mt = 0; mt < 2; mt++) {
        const int mrow = m0 + mw + mt * 16 + g;
#pragma unroll
        for (int j = 0; j < 8; j++) {
            const int ncol = nw + j * 8 + tg * 2;
            const float b0 = s_bias[ncol];
            const float b1 = s_bias[ncol + 1];
            float2 lo, hi;
            lo.x = tanhf(c[mt][j][0] + b0);
            lo.y = tanhf(c[mt][j][1] + b1);
            hi.x = tanhf(c[mt][j][2] + b0);
            hi.y = tanhf(c[mt][j][3] + b1);
            *reinterpret_cast<float2*>(&g_pooled[(size_t)mrow * HH + n0 + ncol]) = lo;
            *reinterpret_cast<float2*>(&g_pooled[(size_t)(mrow + 8) * HH + n0 + ncol]) = hi;
        }
    }
}

// ---------------------------------------------------------------------------
// Span-mean pooling + passage copy + mask. 192 threads, float4/thread, 4-row MLP.
// ---------------------------------------------------------------------------
#define PB_SENT (NB * SS)   // 1024

__global__ __launch_bounds__(192) void pool_kernel(
    const int* __restrict__ spans, float* __restrict__ out) {
    const int bx = blockIdx.x;
    const int tid = threadIdx.x;

    if (bx < PB_SENT) {
        const int n = bx >> 4;
        const int s = bx & 15;

        const int start = spans[(n * SS + s) * 2 + 0];
        const int end   = spans[(n * SS + s) * 2 + 1];
        const float inv = 1.0f / (float)(end - start);

        const float* base = &g_pooled[(size_t)(n * LL) * HH + 4 * tid];
        float4 a = make_float4(0.f, 0.f, 0.f, 0.f);
        int l = start;
        for (; l + 3 < end; l += 4) {
            float4 v0 = *reinterpret_cast<const float4*>(base + (size_t)l * HH);
            float4 v1 = *reinterpret_cast<const float4*>(base + (size_t)(l + 1) * HH);
            float4 v2 = *reinterpret_cast<const float4*>(base + (size_t)(l + 2) * HH);
            float4 v3 = *reinterpret_cast<const float4*>(base + (size_t)(l + 3) * HH);
            a.x += (v0.x + v1.x) + (v2.x + v3.x);
            a.y += (v0.y + v1.y) + (v2.y + v3.y);
            a.z += (v0.z + v1.z) + (v2.z + v3.z);
            a.w += (v0.w + v1.w) + (v2.w + v3.w);
        }
        for (; l < end; l++) {
            float4 v0 = *reinterpret_cast<const float4*>(base + (size_t)l * HH);
            a.x += v0.x; a.y += v0.y; a.z += v0.z; a.w += v0.w;
        }
        a.x *= inv; a.y *= inv; a.z *= inv; a.w *= inv;
        *reinterpret_cast<float4*>(&out[SENT_OFF + (size_t)(n * SS + s) * HH + 4 * tid]) = a;
    } else {
        const int n = bx - PB_SENT;
        const float4 v = *reinterpret_cast<const float4*>(
            &g_pooled[(size_t)(n * LL) * HH + 4 * tid]);
        *reinterpret_cast<float4*>(&out[PASS_OFF + n * HH + 4 * tid]) = v;
        if (tid < SS) out[MASK_OFF + n * SS + tid] = 0.0f;
    }
}

// ---------------------------------------------------------------------------
// Launch
// ---------------------------------------------------------------------------
extern "C" void kernel_launch(void* const* d_in, const int* in_sizes, int n_in,
                              void* d_out, int out_size) {
    const float* hs    = (const float*)d_in[0];
    const float* w     = (const float*)d_in[1];
    const float* b     = (const float*)d_in[2];
    const int*   spans = (const int*)d_in[4];
    float* out = (float*)d_out;

    cudaFuncSetAttribute(gemm_kernel,
                         cudaFuncAttributeMaxDynamicSharedMemorySize, DYN_SMEM);

    const int x4 = M_TOTAL * HH / 4;
    const int w4 = HH * HH / 4;
    convert_x_kernel<<<(x4 + 255) / 256, 256>>>(hs);
    convert_w_kernel<<<(w4 + 255) / 256, 256>>>(w);

    dim3 grid(HH / BN, M_TOTAL / BM);     // (6, 256)
    gemm_kernel<<<grid, 256, DYN_SMEM>>>(b);

    pool_kernel<<<PB_SENT + NB, 192>>>(spans, out);
}

// round 6
// speedup vs baseline: 4.9678x; 1.4418x over previous
#include <cuda_runtime.h>
#include <cuda_fp16.h>
#include <cstdint>

// ---------------------------------------------------------------------------
// Problem constants
// ---------------------------------------------------------------------------
#define NB 64
#define LL 512
#define SS 16
#define HH 768
#define M_TOTAL (NB * LL)          // 32768

#define PASS_OFF 0
#define SENT_OFF (NB * HH)
#define MASK_OFF (NB * HH + NB * SS * HH)

// GEMM tiling: CTA 128x128, warp 32x64 (8 warps: 4 over M, 2 over N), BK=32
#define BM 128
#define BN 128
#define BK 32
#define NKCH (HH / BK)             // 24
#define ROWB 80                    // 32 halves (64B) padded to 80B
#define OFF_AH 0
#define OFF_BH (128 * ROWB)        // 10240
#define STAGE_B (2 * 128 * ROWB)   // 20480
#define NSTAGE 2
#define DYN_SMEM (NSTAGE * STAGE_B)   // 40960 -> 2 CTAs/SM (reg-capped)

// ---------------------------------------------------------------------------
// Device scratch
// ---------------------------------------------------------------------------
__device__ float  g_pooled[(size_t)M_TOTAL * HH];  // 96 MB
__device__ __half g_xh[(size_t)M_TOTAL * HH];      // 48 MB
__device__ __half g_wh[HH * HH];

// ---------------------------------------------------------------------------
// PTX helpers
// ---------------------------------------------------------------------------
__device__ __forceinline__ uint32_t smem_u32(const void* p) {
    uint32_t a;
    asm("{ .reg .u64 t; cvta.to.shared.u64 t, %1; cvt.u32.u64 %0, t; }"
        : "=r"(a) : "l"(p));
    return a;
}

__device__ __forceinline__ void cp16(uint32_t saddr, const void* g) {
    asm volatile("cp.async.cg.shared.global [%0], [%1], 16;"
                 :: "r"(saddr), "l"(g) : "memory");
}

#define CP_COMMIT() asm volatile("cp.async.commit_group;" ::: "memory")

#define LDSM_X4(r0, r1, r2, r3, addr) \
    asm volatile("ldmatrix.sync.aligned.m8n8.x4.shared.b16 {%0,%1,%2,%3}, [%4];" \
                 : "=r"(r0), "=r"(r1), "=r"(r2), "=r"(r3) : "r"(addr))

#define MMA16816(c, a, b0, b1) \
    asm volatile("mma.sync.aligned.m16n8k16.row.col.f32.f16.f16.f32 " \
                 "{%0,%1,%2,%3}, {%4,%5,%6,%7}, {%8,%9}, {%0,%1,%2,%3};" \
                 : "+f"((c)[0]), "+f"((c)[1]), "+f"((c)[2]), "+f"((c)[3]) \
                 : "r"((a)[0]), "r"((a)[1]), "r"((a)[2]), "r"((a)[3]), \
                   "r"(b0), "r"(b1))

// ---------------------------------------------------------------------------
// Conversions: fp32 -> fp16 (round-to-nearest)
// ---------------------------------------------------------------------------
__global__ __launch_bounds__(256) void convert_x_kernel(const float* __restrict__ src) {
    size_t i = (size_t)blockIdx.x * blockDim.x + threadIdx.x;
    const size_t n4 = (size_t)M_TOTAL * HH / 4;
    if (i >= n4) return;
    float4 v = reinterpret_cast<const float4*>(src)[i];
    reinterpret_cast<__half2*>(g_xh)[2 * i] =
        __half2(__float2half_rn(v.x), __float2half_rn(v.y));
    reinterpret_cast<__half2*>(g_xh)[2 * i + 1] =
        __half2(__float2half_rn(v.z), __float2half_rn(v.w));
}

__global__ __launch_bounds__(256) void convert_w_kernel(const float* __restrict__ src) {
    size_t i = (size_t)blockIdx.x * blockDim.x + threadIdx.x;
    const size_t n4 = (size_t)HH * HH / 4;
    if (i >= n4) return;
    float4 v = reinterpret_cast<const float4*>(src)[i];
    reinterpret_cast<__half2*>(g_wh)[2 * i] =
        __half2(__float2half_rn(v.x), __float2half_rn(v.y));
    reinterpret_cast<__half2*>(g_wh)[2 * i + 1] =
        __half2(__float2half_rn(v.z), __float2half_rn(v.w));
}

// ---------------------------------------------------------------------------
// GEMM: g_pooled[m, n] = tanh( X[m, :] . W[n, :] + b[n] )
// Single-pass fp16 mma.sync, fp32 accumulate.
// CTA 128x128, warp 32x64, 2-stage cp.async, 2 CTAs/SM.
// ---------------------------------------------------------------------------
__device__ __forceinline__ void load_stage(uint32_t sb, int k0, int m0, int n0) {
    const int t = threadIdx.x;
#pragma unroll
    for (int i = 0; i < 2; i++) {
        int c = t + 256 * i;
        int row = c >> 2, ch = c & 3;
        uint32_t so = (uint32_t)(row * ROWB + ch * 16);
        cp16(sb + OFF_AH + so, g_xh + (size_t)(m0 + row) * HH + k0 + ch * 8);
        cp16(sb + OFF_BH + so, g_wh + (size_t)(n0 + row) * HH + k0 + ch * 8);
    }
    CP_COMMIT();
}

__global__ __launch_bounds__(256, 2) void gemm_kernel(const float* __restrict__ bias) {
    extern __shared__ char dsm[];
    __shared__ float s_bias[BN];

    const int tid = threadIdx.x;
    const int wid = tid >> 5;
    const int lane = tid & 31;
    const int m0 = blockIdx.y * BM;
    const int n0 = blockIdx.x * BN;

    const int mw = (wid >> 1) * 32;  // 4 warps over M
    const int nw = (wid & 1) * 64;   // 2 warps over N

    const uint32_t sbase = smem_u32(dsm);

    if (tid < BN) s_bias[tid] = bias[n0 + tid];

    float c[2][8][4];
#pragma unroll
    for (int mt = 0; mt < 2; mt++)
#pragma unroll
        for (int j = 0; j < 8; j++)
#pragma unroll
            for (int r = 0; r < 4; r++) c[mt][j][r] = 0.0f;

    const uint32_t a_row = (uint32_t)(mw + (lane & 15)) * ROWB;
    const uint32_t a_col = ((lane >> 4) & 1) * 16;
    const uint32_t b_row = (uint32_t)(nw + (lane & 7) + ((lane >> 4) & 1) * 8) * ROWB;
    const uint32_t b_col = ((lane >> 3) & 1) * 16;

    load_stage(sbase, 0, m0, n0);

    for (int kt = 0; kt < NKCH; kt++) {
        __syncthreads();
        if (kt + 1 < NKCH)
            load_stage(sbase + (uint32_t)((kt + 1) & 1) * STAGE_B, (kt + 1) * BK, m0, n0);
        if (kt + 1 < NKCH) asm volatile("cp.async.wait_group 1;" ::: "memory");
        else               asm volatile("cp.async.wait_group 0;" ::: "memory");
        __syncthreads();

        const uint32_t sb = sbase + (uint32_t)(kt & 1) * STAGE_B;

#pragma unroll
        for (int ks = 0; ks < 2; ks++) {
            const uint32_t kb = (uint32_t)ks * 32;   // 16 halves = 32 bytes
            uint32_t ah[2][4], bh[4][4];
#pragma unroll
            for (int mt = 0; mt < 2; mt++) {
                uint32_t ra = sb + OFF_AH + a_row + (uint32_t)(mt * 16) * ROWB + kb + a_col;
                LDSM_X4(ah[mt][0], ah[mt][1], ah[mt][2], ah[mt][3], ra);
            }
#pragma unroll
            for (int nt = 0; nt < 4; nt++) {
                uint32_t rb = sb + OFF_BH + b_row + (uint32_t)(nt * 16) * ROWB + kb + b_col;
                LDSM_X4(bh[nt][0], bh[nt][1], bh[nt][2], bh[nt][3], rb);
            }
#pragma unroll
            for (int mt = 0; mt < 2; mt++) {
#pragma unroll
                for (int nt = 0; nt < 4; nt++) {
                    MMA16816(c[mt][2 * nt],     ah[mt], bh[nt][0], bh[nt][1]);
                    MMA16816(c[mt][2 * nt + 1], ah[mt], bh[nt][2], bh[nt][3]);
                }
            }
        }
    }
    __syncthreads();

    // Epilogue: bias + tanh, fp32 stores to scratch.
    const int g = lane >> 2;
    const int tg = lane & 3;
#pragma unroll
    for (int mt = 0; mt < 2; mt++) {
        const int mrow = m0 + mw + mt * 16 + g;
#pragma unroll
        for (int j = 0; j < 8; j++) {
            const int ncol = nw + j * 8 + tg * 2;
            const float b0 = s_bias[ncol];
            const float b1 = s_bias[ncol + 1];
            float2 lo, hi;
            lo.x = tanhf(c[mt][j][0] + b0);
            lo.y = tanhf(c[mt][j][1] + b1);
            hi.x = tanhf(c[mt][j][2] + b0);
            hi.y = tanhf(c[mt][j][3] + b1);
            *reinterpret_cast<float2*>(&g_pooled[(size_t)mrow * HH + n0 + ncol]) = lo;
            *reinterpret_cast<float2*>(&g_pooled[(size_t)(mrow + 8) * HH + n0 + ncol]) = hi;
        }
    }
}

// ---------------------------------------------------------------------------
// Span-mean pooling + passage copy + mask. 192 threads, float4/thread, 8-row MLP.
// ---------------------------------------------------------------------------
#define PB_SENT (NB * SS)   // 1024

__global__ __launch_bounds__(192) void pool_kernel(
    const int* __restrict__ spans, float* __restrict__ out) {
    const int bx = blockIdx.x;
    const int tid = threadIdx.x;

    if (bx < PB_SENT) {
        const int n = bx >> 4;
        const int s = bx & 15;

        const int start = spans[(n * SS + s) * 2 + 0];
        const int end   = spans[(n * SS + s) * 2 + 1];
        const float inv = 1.0f / (float)(end - start);

        const float* base = &g_pooled[(size_t)(n * LL) * HH + 4 * tid];
        float4 a = make_float4(0.f, 0.f, 0.f, 0.f);
        int l = start;
        for (; l + 7 < end; l += 8) {
            float4 v[8];
#pragma unroll
            for (int u = 0; u < 8; u++)
                v[u] = *reinterpret_cast<const float4*>(base + (size_t)(l + u) * HH);
#pragma unroll
            for (int u = 0; u < 8; u++) {
                a.x += v[u].x; a.y += v[u].y; a.z += v[u].z; a.w += v[u].w;
            }
        }
        for (; l < end; l++) {
            float4 v0 = *reinterpret_cast<const float4*>(base + (size_t)l * HH);
            a.x += v0.x; a.y += v0.y; a.z += v0.z; a.w += v0.w;
        }
        a.x *= inv; a.y *= inv; a.z *= inv; a.w *= inv;
        *reinterpret_cast<float4*>(&out[SENT_OFF + (size_t)(n * SS + s) * HH + 4 * tid]) = a;
    } else {
        const int n = bx - PB_SENT;
        const float4 v = *reinterpret_cast<const float4*>(
            &g_pooled[(size_t)(n * LL) * HH + 4 * tid]);
        *reinterpret_cast<float4*>(&out[PASS_OFF + n * HH + 4 * tid]) = v;
        if (tid < SS) out[MASK_OFF + n * SS + tid] = 0.0f;
    }
}

// ---------------------------------------------------------------------------
// Launch
// ---------------------------------------------------------------------------
extern "C" void kernel_launch(void* const* d_in, const int* in_sizes, int n_in,
                              void* d_out, int out_size) {
    const float* hs    = (const float*)d_in[0];
    const float* w     = (const float*)d_in[1];
    const float* b     = (const float*)d_in[2];
    const int*   spans = (const int*)d_in[4];
    float* out = (float*)d_out;

    cudaFuncSetAttribute(gemm_kernel,
                         cudaFuncAttributeMaxDynamicSharedMemorySize, DYN_SMEM);

    const int x4 = M_TOTAL * HH / 4;
    const int w4 = HH * HH / 4;
    convert_x_kernel<<<(x4 + 255) / 256, 256>>>(hs);
    convert_w_kernel<<<(w4 + 255) / 256, 256>>>(w);

    dim3 grid(HH / BN, M_TOTAL / BM);     // (6, 256)
    gemm_kernel<<<grid, 256, DYN_SMEM>>>(b);

    pool_kernel<<<PB_SENT + NB, 192>>>(spans, out);
}

// round 7
// speedup vs baseline: 5.2963x; 1.0661x over previous
#include <cuda_runtime.h>
#include <cuda_fp16.h>
#include <cstdint>

// ---------------------------------------------------------------------------
// Problem constants
// ---------------------------------------------------------------------------
#define NB 64
#define LL 512
#define SS 16
#define HH 768
#define M_TOTAL (NB * LL)          // 32768

#define PASS_OFF 0
#define SENT_OFF (NB * HH)
#define MASK_OFF (NB * HH + NB * SS * HH)
#define OUT_TOTAL (NB * HH + NB * SS * HH + NB * SS)   // 836608

// GEMM tiling: CTA 128x128, warp 32x64 (8 warps: 4 over M, 2 over N), BK=32
#define BM 128
#define BN 128
#define BK 32
#define NKCH (HH / BK)             // 24
#define ROWB 80                    // 32 halves (64B) padded to 80B
#define OFF_AH 0
#define OFF_BH (128 * ROWB)        // 10240
#define STAGE_B (2 * 128 * ROWB)   // 20480
#define NSTAGE 2
#define DYN_SMEM (NSTAGE * STAGE_B)   // 40960 -> 2 CTAs/SM

// ---------------------------------------------------------------------------
// Device scratch
// ---------------------------------------------------------------------------
__device__ __half g_xh[(size_t)M_TOTAL * HH];      // 48 MB
__device__ __half g_wh[HH * HH];

// ---------------------------------------------------------------------------
// PTX helpers
// ---------------------------------------------------------------------------
__device__ __forceinline__ uint32_t smem_u32(const void* p) {
    uint32_t a;
    asm("{ .reg .u64 t; cvta.to.shared.u64 t, %1; cvt.u32.u64 %0, t; }"
        : "=r"(a) : "l"(p));
    return a;
}

__device__ __forceinline__ void cp16(uint32_t saddr, const void* g) {
    asm volatile("cp.async.cg.shared.global [%0], [%1], 16;"
                 :: "r"(saddr), "l"(g) : "memory");
}

#define CP_COMMIT() asm volatile("cp.async.commit_group;" ::: "memory")

#define LDSM_X4(r0, r1, r2, r3, addr) \
    asm volatile("ldmatrix.sync.aligned.m8n8.x4.shared.b16 {%0,%1,%2,%3}, [%4];" \
                 : "=r"(r0), "=r"(r1), "=r"(r2), "=r"(r3) : "r"(addr))

#define MMA16816(c, a, b0, b1) \
    asm volatile("mma.sync.aligned.m16n8k16.row.col.f32.f16.f16.f32 " \
                 "{%0,%1,%2,%3}, {%4,%5,%6,%7}, {%8,%9}, {%0,%1,%2,%3};" \
                 : "+f"((c)[0]), "+f"((c)[1]), "+f"((c)[2]), "+f"((c)[3]) \
                 : "r"((a)[0]), "r"((a)[1]), "r"((a)[2]), "r"((a)[3]), \
                   "r"(b0), "r"(b1))

// ---------------------------------------------------------------------------
// Zero-init of output (sentence region accumulates via atomics; mask = 0;
// passage region fully overwritten, but zeroing everything is simplest).
// ---------------------------------------------------------------------------
__global__ __launch_bounds__(256) void init_out_kernel(float* __restrict__ out) {
    size_t i = (size_t)blockIdx.x * blockDim.x + threadIdx.x;
    const size_t n4 = OUT_TOTAL / 4;   // 209152
    if (i < n4)
        reinterpret_cast<float4*>(out)[i] = make_float4(0.f, 0.f, 0.f, 0.f);
}

// ---------------------------------------------------------------------------
// Conversions: fp32 -> fp16 (round-to-nearest)
// ---------------------------------------------------------------------------
__global__ __launch_bounds__(256) void convert_x_kernel(const float* __restrict__ src) {
    size_t i = (size_t)blockIdx.x * blockDim.x + threadIdx.x;
    const size_t n4 = (size_t)M_TOTAL * HH / 4;
    if (i >= n4) return;
    float4 v = reinterpret_cast<const float4*>(src)[i];
    reinterpret_cast<__half2*>(g_xh)[2 * i] =
        __half2(__float2half_rn(v.x), __float2half_rn(v.y));
    reinterpret_cast<__half2*>(g_xh)[2 * i + 1] =
        __half2(__float2half_rn(v.z), __float2half_rn(v.w));
}

__global__ __launch_bounds__(256) void convert_w_kernel(const float* __restrict__ src) {
    size_t i = (size_t)blockIdx.x * blockDim.x + threadIdx.x;
    const size_t n4 = (size_t)HH * HH / 4;
    if (i >= n4) return;
    float4 v = reinterpret_cast<const float4*>(src)[i];
    reinterpret_cast<__half2*>(g_wh)[2 * i] =
        __half2(__float2half_rn(v.x), __float2half_rn(v.y));
    reinterpret_cast<__half2*>(g_wh)[2 * i + 1] =
        __half2(__float2half_rn(v.z), __float2half_rn(v.w));
}

// ---------------------------------------------------------------------------
// GEMM + fused pooling epilogue.
//   val = tanh(X.W^T + b); passage rows (l==0) -> out directly;
//   covered rows -> atomicAdd(val * inv_count) into sentence region.
// ---------------------------------------------------------------------------
__device__ __forceinline__ void load_stage(uint32_t sb, int k0, int m0, int n0) {
    const int t = threadIdx.x;
#pragma unroll
    for (int i = 0; i < 2; i++) {
        int c = t + 256 * i;
        int row = c >> 2, ch = c & 3;
        uint32_t so = (uint32_t)(row * ROWB + ch * 16);
        cp16(sb + OFF_AH + so, g_xh + (size_t)(m0 + row) * HH + k0 + ch * 8);
        cp16(sb + OFF_BH + so, g_wh + (size_t)(n0 + row) * HH + k0 + ch * 8);
    }
    CP_COMMIT();
}

__global__ __launch_bounds__(256, 2) void gemm_kernel(
    const float* __restrict__ bias,
    const int* __restrict__ spans,
    float* __restrict__ out)
{
    extern __shared__ char dsm[];
    __shared__ float s_bias[BN];
    __shared__ int   s_sp[SS * 2];
    __shared__ float s_inv[SS];

    const int tid = threadIdx.x;
    const int wid = tid >> 5;
    const int lane = tid & 31;
    const int m0 = blockIdx.y * BM;
    const int n0 = blockIdx.x * BN;
    const int nidx = m0 >> 9;          // sample index (512 rows per n)
    const int ltile = m0 & 511;        // tile's row offset within the sample

    const int mw = (wid >> 1) * 32;
    const int nw = (wid & 1) * 64;

    const uint32_t sbase = smem_u32(dsm);

    if (tid < BN) s_bias[tid] = bias[n0 + tid];
    if (tid < SS * 2) s_sp[tid] = spans[nidx * SS * 2 + tid];
    if (tid >= 64 && tid < 64 + SS) {
        int s = tid - 64;
        int st = spans[(nidx * SS + s) * 2];
        int en = spans[(nidx * SS + s) * 2 + 1];
        s_inv[s] = 1.0f / (float)(en - st);
    }

    float c[2][8][4];
#pragma unroll
    for (int mt = 0; mt < 2; mt++)
#pragma unroll
        for (int j = 0; j < 8; j++)
#pragma unroll
            for (int r = 0; r < 4; r++) c[mt][j][r] = 0.0f;

    const uint32_t a_row = (uint32_t)(mw + (lane & 15)) * ROWB;
    const uint32_t a_col = ((lane >> 4) & 1) * 16;
    const uint32_t b_row = (uint32_t)(nw + (lane & 7) + ((lane >> 4) & 1) * 8) * ROWB;
    const uint32_t b_col = ((lane >> 3) & 1) * 16;

    load_stage(sbase, 0, m0, n0);

    for (int kt = 0; kt < NKCH; kt++) {
        __syncthreads();
        if (kt + 1 < NKCH)
            load_stage(sbase + (uint32_t)((kt + 1) & 1) * STAGE_B, (kt + 1) * BK, m0, n0);
        if (kt + 1 < NKCH) asm volatile("cp.async.wait_group 1;" ::: "memory");
        else               asm volatile("cp.async.wait_group 0;" ::: "memory");
        __syncthreads();

        const uint32_t sb = sbase + (uint32_t)(kt & 1) * STAGE_B;

#pragma unroll
        for (int ks = 0; ks < 2; ks++) {
            const uint32_t kb = (uint32_t)ks * 32;
            uint32_t ah[2][4], bh[4][4];
#pragma unroll
            for (int mt = 0; mt < 2; mt++) {
                uint32_t ra = sb + OFF_AH + a_row + (uint32_t)(mt * 16) * ROWB + kb + a_col;
                LDSM_X4(ah[mt][0], ah[mt][1], ah[mt][2], ah[mt][3], ra);
            }
#pragma unroll
            for (int nt = 0; nt < 4; nt++) {
                uint32_t rb = sb + OFF_BH + b_row + (uint32_t)(nt * 16) * ROWB + kb + b_col;
                LDSM_X4(bh[nt][0], bh[nt][1], bh[nt][2], bh[nt][3], rb);
            }
#pragma unroll
            for (int mt = 0; mt < 2; mt++) {
#pragma unroll
                for (int nt = 0; nt < 4; nt++) {
                    MMA16816(c[mt][2 * nt],     ah[mt], bh[nt][0], bh[nt][1]);
                    MMA16816(c[mt][2 * nt + 1], ah[mt], bh[nt][2], bh[nt][3]);
                }
            }
        }
    }
    __syncthreads();

    // ----- Fused epilogue -----
    const int g = lane >> 2;
    const int tg = lane & 3;

    // Span lookup for the 4 rows this thread owns: (mt, half) -> l
    int   sid[2][2];
    float siv[2][2];
    int   lrow[2][2];
#pragma unroll
    for (int mt = 0; mt < 2; mt++) {
#pragma unroll
        for (int hf = 0; hf < 2; hf++) {
            const int l = ltile + mw + mt * 16 + g + hf * 8;
            lrow[mt][hf] = l;
            int found = -1;
#pragma unroll
            for (int s = 0; s < SS; s++) {
                if (l >= s_sp[2 * s] && l < s_sp[2 * s + 1]) found = s;
            }
            sid[mt][hf] = found;
            siv[mt][hf] = (found >= 0) ? s_inv[found] : 0.0f;
        }
    }

#pragma unroll
    for (int mt = 0; mt < 2; mt++) {
#pragma unroll
        for (int j = 0; j < 8; j++) {
            const int ncol = n0 + nw + j * 8 + tg * 2;
            const float b0 = s_bias[nw + j * 8 + tg * 2];
            const float b1 = s_bias[nw + j * 8 + tg * 2 + 1];
            const float v00 = tanhf(c[mt][j][0] + b0);   // row (mt, hf=0)
            const float v01 = tanhf(c[mt][j][1] + b1);
            const float v10 = tanhf(c[mt][j][2] + b0);   // row (mt, hf=1)
            const float v11 = tanhf(c[mt][j][3] + b1);

            // Passage output: row l == 0
            if (lrow[mt][0] == 0) {
                out[PASS_OFF + nidx * HH + ncol]     = v00;
                out[PASS_OFF + nidx * HH + ncol + 1] = v01;
            }
            // Sentence accumulation
            if (sid[mt][0] >= 0) {
                float* dst = &out[SENT_OFF + (size_t)(nidx * SS + sid[mt][0]) * HH + ncol];
                atomicAdd(dst,     v00 * siv[mt][0]);
                atomicAdd(dst + 1, v01 * siv[mt][0]);
            }
            if (sid[mt][1] >= 0) {
                float* dst = &out[SENT_OFF + (size_t)(nidx * SS + sid[mt][1]) * HH + ncol];
                atomicAdd(dst,     v10 * siv[mt][1]);
                atomicAdd(dst + 1, v11 * siv[mt][1]);
            }
        }
    }
}

// ---------------------------------------------------------------------------
// Launch
// ---------------------------------------------------------------------------
extern "C" void kernel_launch(void* const* d_in, const int* in_sizes, int n_in,
                              void* d_out, int out_size) {
    const float* hs    = (const float*)d_in[0];
    const float* w     = (const float*)d_in[1];
    const float* b     = (const float*)d_in[2];
    const int*   spans = (const int*)d_in[4];
    float* out = (float*)d_out;

    cudaFuncSetAttribute(gemm_kernel,
                         cudaFuncAttributeMaxDynamicSharedMemorySize, DYN_SMEM);

    const int o4 = OUT_TOTAL / 4;
    init_out_kernel<<<(o4 + 255) / 256, 256>>>(out);

    const int x4 = M_TOTAL * HH / 4;
    const int w4 = HH * HH / 4;
    convert_x_kernel<<<(x4 + 255) / 256, 256>>>(hs);
    convert_w_kernel<<<(w4 + 255) / 256, 256>>>(w);

    dim3 grid(HH / BN, M_TOTAL / BM);     // (6, 256)
    gemm_kernel<<<grid, 256, DYN_SMEM>>>(b, spans, out);
}